// round 1
// baseline (speedup 1.0000x reference)
#include <cuda_runtime.h>
#include <cuda_bf16.h>
#include <math.h>

// Problem constants
#define BSZ 2
#define LSEQ 1024
#define DMODEL 1024
#define DINNER 2048
#define NSTATE 16
#define DTRANK 64
#define KCONV 3
#define CHUNK 256
#define NTOK (BSZ*LSEQ)          // 2048
#define XPC (DTRANK + 2*NSTATE)  // 96

// Scratch (device globals; no allocation allowed)
__device__ float g_xr[(size_t)NTOK * 2 * DINNER];   // (B,L,4096): xc | res
__device__ float g_u[(size_t)NTOK * DINNER];        // (B,L,2048)
__device__ float g_xp[(size_t)NTOK * XPC];          // (B,L,96)
__device__ float g_delta[(size_t)NTOK * DINNER];    // (B,L,2048)
__device__ float g_y[(size_t)NTOK * DINNER];        // (B,L,2048)

__device__ __forceinline__ float silu_f(float x) {
    return x / (1.0f + __expf(-x));
}

// ---------------------------------------------------------------------------
// Generic fp32 NT GEMM: C[m,n] = act( sum_k A[m,k]*W[n,k] + bias[n] )
// A optionally gated elementwise: A'[m,k] = A[m,k] * silu(G[m,k])
// BM=128, BN=64, BK=16, 256 threads, 8x4 register tile per thread.
// Requires: M % 128 == 0, K % 16 == 0, lda/ldw/ldg rows 16B-aligned.
// ---------------------------------------------------------------------------
#define GBM 128
#define GBN 64
#define GBK 16

template<int ACT, bool GATE>
__global__ __launch_bounds__(256, 2)
void gemm_nt_kernel(const float* __restrict__ A, int lda,
                    const float* __restrict__ G, int ldg,
                    const float* __restrict__ W, int ldw,
                    const float* __restrict__ bias,
                    float* __restrict__ C, int ldc,
                    int N, int K) {
    __shared__ float As[GBK][GBM + 4];
    __shared__ float Ws[GBK][GBN + 4];

    const int tid = threadIdx.x;
    const int bm = blockIdx.y * GBM;
    const int bn = blockIdx.x * GBN;
    const int tx = tid & 15;   // n group (0..15)
    const int ty = tid >> 4;   // m group (0..15)

    float acc[8][4];
#pragma unroll
    for (int i = 0; i < 8; i++)
#pragma unroll
        for (int j = 0; j < 4; j++) acc[i][j] = 0.0f;

    const int lk = tid & 3;    // k-quad
    const int lr = tid >> 2;   // row 0..63

    for (int k0 = 0; k0 < K; k0 += GBK) {
        // --- load A tile (128 x 16), transposed into As[k][m] ---
#pragma unroll
        for (int p = 0; p < 2; p++) {
            int r = lr + p * 64;
            int m = bm + r;
            float4 v = *(const float4*)(A + (size_t)m * lda + k0 + lk * 4);
            if (GATE) {
                float4 g = *(const float4*)(G + (size_t)m * ldg + k0 + lk * 4);
                v.x *= silu_f(g.x); v.y *= silu_f(g.y);
                v.z *= silu_f(g.z); v.w *= silu_f(g.w);
            }
            As[lk * 4 + 0][r] = v.x;
            As[lk * 4 + 1][r] = v.y;
            As[lk * 4 + 2][r] = v.z;
            As[lk * 4 + 3][r] = v.w;
        }
        // --- load W tile (64 x 16), transposed into Ws[k][n] ---
        {
            int nrow = lr;
            float4 v = make_float4(0.f, 0.f, 0.f, 0.f);
            if (bn + nrow < N)
                v = *(const float4*)(W + (size_t)(bn + nrow) * ldw + k0 + lk * 4);
            Ws[lk * 4 + 0][nrow] = v.x;
            Ws[lk * 4 + 1][nrow] = v.y;
            Ws[lk * 4 + 2][nrow] = v.z;
            Ws[lk * 4 + 3][nrow] = v.w;
        }
        __syncthreads();

#pragma unroll
        for (int kk = 0; kk < GBK; kk++) {
            float4 a0 = *(const float4*)&As[kk][ty * 4];
            float4 a1 = *(const float4*)&As[kk][64 + ty * 4];
            float4 b0 = *(const float4*)&Ws[kk][tx * 4];
            float am[8] = {a0.x, a0.y, a0.z, a0.w, a1.x, a1.y, a1.z, a1.w};
            float bn_[4] = {b0.x, b0.y, b0.z, b0.w};
#pragma unroll
            for (int i = 0; i < 8; i++)
#pragma unroll
                for (int j = 0; j < 4; j++)
                    acc[i][j] = fmaf(am[i], bn_[j], acc[i][j]);
        }
        __syncthreads();
    }

    // epilogue
#pragma unroll
    for (int i = 0; i < 8; i++) {
        int m = bm + ((i < 4) ? (ty * 4 + i) : (64 + ty * 4 + (i - 4)));
#pragma unroll
        for (int j = 0; j < 4; j++) {
            int n = bn + tx * 4 + j;
            if (n < N) {
                float v = acc[i][j];
                if (bias) v += bias[n];
                if (ACT == 1) {  // softplus
                    v = (v > 20.0f) ? v : log1pf(__expf(v));
                }
                C[(size_t)m * ldc + n] = v;
            }
        }
    }
}

// ---------------------------------------------------------------------------
// Depthwise causal conv1d (k=3) + bias + SiLU.  xc = g_xr[:, :, 0:2048]
// ---------------------------------------------------------------------------
__global__ void conv_silu_kernel(const float* __restrict__ cw,
                                 const float* __restrict__ cb,
                                 float* __restrict__ u) {
    int idx = blockIdx.x * blockDim.x + threadIdx.x;  // over NTOK*DINNER
    if (idx >= NTOK * DINNER) return;
    int d = idx & (DINNER - 1);
    int bl = idx >> 11;            // DINNER = 2048 = 2^11
    int l = bl & (LSEQ - 1);

    float w0 = __ldg(cw + d * 3 + 0);
    float w1 = __ldg(cw + d * 3 + 1);
    float w2 = __ldg(cw + d * 3 + 2);

    const float* base = g_xr + (size_t)bl * (2 * DINNER) + d;
    float acc = __ldg(cb + d) + w2 * base[0];
    if (l >= 1) acc = fmaf(w1, base[-(2 * DINNER)], acc);
    if (l >= 2) acc = fmaf(w0, base[-(4 * DINNER)], acc);
    u[idx] = silu_f(acc);
}

// ---------------------------------------------------------------------------
// Chunked selective scan. One thread per d, 16 states in registers.
// grid = (DINNER/128, L/CHUNK, B), block = 128
// ---------------------------------------------------------------------------
__global__ __launch_bounds__(128)
void scan_kernel(const float* __restrict__ A_log,
                 float* __restrict__ y) {
    __shared__ float sBC[CHUNK][2 * NSTATE];   // 32 KB: [t][0:16]=B, [16:32]=C

    const int b = blockIdx.z;
    const int c = blockIdx.y;
    const int d = blockIdx.x * 128 + threadIdx.x;
    const int l0 = c * CHUNK;
    const size_t row0 = (size_t)(b * LSEQ + l0);

    // stage B,C for the whole chunk
    for (int i = threadIdx.x; i < CHUNK * 32; i += 128) {
        int t = i >> 5, j = i & 31;
        sBC[t][j] = g_xp[(row0 + t) * XPC + DTRANK + j];
    }

    float A[NSTATE];
#pragma unroll
    for (int n = 0; n < NSTATE; n++)
        A[n] = -__expf(__ldg(A_log + d * NSTATE + n));

    float s[NSTATE];
#pragma unroll
    for (int n = 0; n < NSTATE; n++) s[n] = 0.0f;

    __syncthreads();

    const float* dp = g_delta + row0 * DINNER + d;
    const float* up = g_u + row0 * DINNER + d;
    float* yp = y + row0 * DINNER + d;

    float dl = dp[0];
    float ut = up[0];
    for (int t = 0; t < CHUNK; t++) {
        // prefetch next step's operands
        float dln = 0.f, utn = 0.f;
        if (t + 1 < CHUNK) {
            dln = dp[(size_t)(t + 1) * DINNER];
            utn = up[(size_t)(t + 1) * DINNER];
        }
        float du = dl * ut;
        float acc = 0.0f;
#pragma unroll
        for (int n = 0; n < NSTATE; n++) {
            float a = __expf(dl * A[n]);
            s[n] = fmaf(a, s[n], du * sBC[t][n]);
            acc = fmaf(s[n], sBC[t][NSTATE + n], acc);
        }
        yp[(size_t)t * DINNER] = acc;
        dl = dln; ut = utn;
    }
}

// ---------------------------------------------------------------------------
// Host launch
// ---------------------------------------------------------------------------
extern "C" void kernel_launch(void* const* d_in, const int* in_sizes, int n_in,
                              void* d_out, int out_size) {
    const float* x      = (const float*)d_in[0];   // (B,L,1024)
    const float* W_in   = (const float*)d_in[1];   // (4096,1024)
    const float* b_in   = (const float*)d_in[2];   // (4096)
    const float* conv_w = (const float*)d_in[3];   // (2048,1,3)
    const float* conv_b = (const float*)d_in[4];   // (2048)
    const float* W_x    = (const float*)d_in[5];   // (96,2048)
    const float* W_dt   = (const float*)d_in[6];   // (2048,64)
    const float* b_dt   = (const float*)d_in[7];   // (2048)
    const float* A_log  = (const float*)d_in[8];   // (2048,16)
    const float* W_out  = (const float*)d_in[9];   // (1024,2048)
    const float* b_out  = (const float*)d_in[10];  // (1024)
    float* out = (float*)d_out;

    float *p_xr, *p_u, *p_xp, *p_delta, *p_y;
    cudaGetSymbolAddress((void**)&p_xr, g_xr);
    cudaGetSymbolAddress((void**)&p_u, g_u);
    cudaGetSymbolAddress((void**)&p_xp, g_xp);
    cudaGetSymbolAddress((void**)&p_delta, g_delta);
    cudaGetSymbolAddress((void**)&p_y, g_y);

    // 1) in_proj: xr = x @ W_in^T + b_in       (2048 x 4096, K=1024)
    {
        dim3 grid((2 * DINNER) / GBN, NTOK / GBM);
        gemm_nt_kernel<0, false><<<grid, 256>>>(
            x, DMODEL, nullptr, 0, W_in, DMODEL, b_in,
            p_xr, 2 * DINNER, 2 * DINNER, DMODEL);
    }
    // 2) depthwise conv + SiLU -> u
    {
        int total = NTOK * DINNER;
        conv_silu_kernel<<<(total + 255) / 256, 256>>>(conv_w, conv_b, p_u);
    }
    // 3) x_proj: xp = u @ W_x^T                (2048 x 96, K=2048)
    {
        dim3 grid((XPC + GBN - 1) / GBN, NTOK / GBM);
        gemm_nt_kernel<0, false><<<grid, 256>>>(
            p_u, DINNER, nullptr, 0, W_x, DINNER, nullptr,
            p_xp, XPC, XPC, DINNER);
    }
    // 4) delta = softplus(dlt @ W_dt^T + b_dt) (2048 x 2048, K=64)
    {
        dim3 grid(DINNER / GBN, NTOK / GBM);
        gemm_nt_kernel<1, false><<<grid, 256>>>(
            p_xp, XPC, nullptr, 0, W_dt, DTRANK, b_dt,
            p_delta, DINNER, DINNER, DTRANK);
    }
    // 5) chunked selective scan -> y
    {
        dim3 grid(DINNER / 128, LSEQ / CHUNK, BSZ);
        scan_kernel<<<grid, 128>>>(A_log, p_y);
    }
    // 6) out = (y * silu(res)) @ W_out^T + b_out  (2048 x 1024, K=2048)
    {
        dim3 grid(DMODEL / GBN, NTOK / GBM);
        gemm_nt_kernel<0, true><<<grid, 256>>>(
            p_y, DINNER, p_xr + DINNER, 2 * DINNER, W_out, DINNER, b_out,
            out, DMODEL, DMODEL, DINNER);
    }
}

// round 3
// speedup vs baseline: 2.3802x; 2.3802x over previous
#include <cuda_runtime.h>
#include <cuda_bf16.h>
#include <math.h>
#include <stdint.h>

// Problem constants
#define BSZ 2
#define LSEQ 1024
#define DMODEL 1024
#define DINNER 2048
#define NSTATE 16
#define DTRANK 64
#define CHUNK 256
#define NTOK (BSZ*LSEQ)          // 2048
#define XPC (DTRANK + 2*NSTATE)  // 96
#define XP_KSPLIT 8

// ---------------------------------------------------------------------------
// Low-level helpers
// ---------------------------------------------------------------------------
__device__ __forceinline__ uint32_t smem_to_u32(const void* p) {
    uint32_t a;
    asm("{ .reg .u64 t; cvta.to.shared.u64 t, %1; cvt.u32.u64 %0, t; }" : "=r"(a) : "l"(p));
    return a;
}
__device__ __forceinline__ void cp16(uint32_t dst, const void* src) {
    asm volatile("cp.async.cg.shared.global [%0], [%1], 16;" :: "r"(dst), "l"(src));
}
__device__ __forceinline__ void ldsm_x4(uint32_t* r, uint32_t addr) {
    asm volatile("ldmatrix.sync.aligned.m8n8.x4.shared.b16 {%0,%1,%2,%3}, [%4];"
                 : "=r"(r[0]), "=r"(r[1]), "=r"(r[2]), "=r"(r[3]) : "r"(addr));
}
__device__ __forceinline__ void mma16816(float* c, const uint32_t* a, const uint32_t* b) {
    asm volatile(
        "mma.sync.aligned.m16n8k16.row.col.f32.bf16.bf16.f32 "
        "{%0,%1,%2,%3}, {%4,%5,%6,%7}, {%8,%9}, {%0,%1,%2,%3};"
        : "+f"(c[0]), "+f"(c[1]), "+f"(c[2]), "+f"(c[3])
        : "r"(a[0]), "r"(a[1]), "r"(a[2]), "r"(a[3]), "r"(b[0]), "r"(b[1]));
}

// ---------------------------------------------------------------------------
// Scratch (device globals)
// ---------------------------------------------------------------------------
__device__ __align__(16) float g_xr[(size_t)NTOK * 2 * DINNER];
__device__ __align__(16) float g_u[(size_t)NTOK * DINNER];
__device__ __align__(16) float g_xp[(size_t)NTOK * XPC];
__device__ __align__(16) float g_xp_part[(size_t)XP_KSPLIT * NTOK * XPC];
__device__ __align__(16) float g_delta[(size_t)NTOK * DINNER];
__device__ __align__(16) float g_y[(size_t)NTOK * DINNER];

__device__ __align__(16) __nv_bfloat16 g_x_hi[(size_t)NTOK * DMODEL];
__device__ __align__(16) __nv_bfloat16 g_x_lo[(size_t)NTOK * DMODEL];
__device__ __align__(16) __nv_bfloat16 g_Win_hi[(size_t)2 * DINNER * DMODEL];
__device__ __align__(16) __nv_bfloat16 g_Win_lo[(size_t)2 * DINNER * DMODEL];
__device__ __align__(16) __nv_bfloat16 g_Wx_hi[(size_t)XPC * DINNER];
__device__ __align__(16) __nv_bfloat16 g_Wx_lo[(size_t)XPC * DINNER];
__device__ __align__(16) __nv_bfloat16 g_Wdt_hi[(size_t)DINNER * DTRANK];
__device__ __align__(16) __nv_bfloat16 g_Wdt_lo[(size_t)DINNER * DTRANK];
__device__ __align__(16) __nv_bfloat16 g_Wout_hi[(size_t)DMODEL * DINNER];
__device__ __align__(16) __nv_bfloat16 g_Wout_lo[(size_t)DMODEL * DINNER];
__device__ __align__(16) __nv_bfloat16 g_u_hi[(size_t)NTOK * DINNER];
__device__ __align__(16) __nv_bfloat16 g_u_lo[(size_t)NTOK * DINNER];
__device__ __align__(16) __nv_bfloat16 g_xp_hi[(size_t)NTOK * XPC];
__device__ __align__(16) __nv_bfloat16 g_xp_lo[(size_t)NTOK * XPC];
__device__ __align__(16) __nv_bfloat16 g_g_hi[(size_t)NTOK * DINNER];
__device__ __align__(16) __nv_bfloat16 g_g_lo[(size_t)NTOK * DINNER];

__device__ __forceinline__ float silu_f(float x) { return x / (1.0f + __expf(-x)); }
__device__ __forceinline__ void split_bf16(float v, __nv_bfloat16& h, __nv_bfloat16& l) {
    h = __float2bfloat16(v);
    l = __float2bfloat16(v - __bfloat162float(h));
}
__device__ __forceinline__ uint32_t pack2(__nv_bfloat16 a, __nv_bfloat16 b) {
    return ((uint32_t)__bfloat16_as_ushort(b) << 16) | (uint32_t)__bfloat16_as_ushort(a);
}

// ---------------------------------------------------------------------------
// Convert fp32 -> (hi, lo) bf16 pair, vectorized x4
// ---------------------------------------------------------------------------
__global__ void cvt_pair_kernel(const float* __restrict__ in,
                                __nv_bfloat16* __restrict__ hi,
                                __nv_bfloat16* __restrict__ lo, int n4) {
    int i = blockIdx.x * blockDim.x + threadIdx.x;
    if (i >= n4) return;
    float4 v = ((const float4*)in)[i];
    __nv_bfloat16 h0, h1, h2, h3, l0, l1, l2, l3;
    split_bf16(v.x, h0, l0); split_bf16(v.y, h1, l1);
    split_bf16(v.z, h2, l2); split_bf16(v.w, h3, l3);
    ((uint2*)hi)[i] = make_uint2(pack2(h0, h1), pack2(h2, h3));
    ((uint2*)lo)[i] = make_uint2(pack2(l0, l1), pack2(l2, l3));
}

// ---------------------------------------------------------------------------
// mma.sync split-bf16 GEMM: C[m,n] = act( sum_k A[m,k]*W[n,k] + bias[n] )
// CTA 128x128, BK=32, 512 threads (16 warps 4x4, warp tile 32x32).
// cp.async double-buffered; XOR swizzle on 16B chunks within 64B rows.
// 3-term accumulation: AhiWhi + AhiWlo + AloWhi (fp32 accum in registers).
// ---------------------------------------------------------------------------
#define STG_BYTES 32768      // per stage: 4 tiles x 8192
#define GEMM_SMEM (2 * STG_BYTES)

__device__ __forceinline__ uint32_t swz(int row, int c) {
    return (uint32_t)(row * 64 + ((c ^ ((row >> 1) & 3)) << 4));
}

template<int ACT>
__global__ __launch_bounds__(512, 1)
void gemm_mma_kernel(const __nv_bfloat16* __restrict__ Ahi, const __nv_bfloat16* __restrict__ Alo, int lda,
                     const __nv_bfloat16* __restrict__ Whi, const __nv_bfloat16* __restrict__ Wlo, int ldw,
                     const float* __restrict__ bias, float* __restrict__ C, int ldc,
                     int Nvalid, int K, long czstride) {
    extern __shared__ __align__(1024) char smem[];
    const uint32_t sbase = smem_to_u32(smem);
    const int tid = threadIdx.x;
    const int lane = tid & 31, wid = tid >> 5;
    const int wm = wid & 3, wn = wid >> 2;
    const int bm = blockIdx.y * 128, bn = blockIdx.x * 128;
    const int kbase = blockIdx.z * K;
    float* Cz = C + (size_t)blockIdx.z * czstride;

    // zero-fill W tile rows >= Nvalid (xp case), both stages, both W tiles
    if (bn + 128 > Nvalid) {
        for (int j = tid; j < 2 * 2 * 128 * 4; j += 512) {
            int c = j & 3, r = (j >> 2) & 127, t = (j >> 9) & 1, s = j >> 10;
            if (bn + r >= Nvalid)
                *(uint4*)(smem + s * STG_BYTES + (2 + t) * 8192 + swz(r, c)) = make_uint4(0, 0, 0, 0);
        }
        __syncthreads();
    }

    const int nIter = K / 32;
    const int r = tid >> 2, c = tid & 3;
    const uint32_t dswz = swz(r, c);
    const bool wok = (bn + r < Nvalid);

    auto issue = [&](int stage, int k0) {
        uint32_t dst = sbase + stage * STG_BYTES + dswz;
        const char* a0 = (const char*)Ahi + ((size_t)(bm + r) * lda + k0) * 2 + c * 16;
        const char* a1 = (const char*)Alo + ((size_t)(bm + r) * lda + k0) * 2 + c * 16;
        cp16(dst, a0);
        cp16(dst + 8192, a1);
        if (wok) {
            const char* w0 = (const char*)Whi + ((size_t)(bn + r) * ldw + k0) * 2 + c * 16;
            const char* w1 = (const char*)Wlo + ((size_t)(bn + r) * ldw + k0) * 2 + c * 16;
            cp16(dst + 16384, w0);
            cp16(dst + 24576, w1);
        }
    };

    issue(0, kbase);
    asm volatile("cp.async.commit_group;" ::: "memory");
    if (nIter > 1) {
        issue(1, kbase + 32);
        asm volatile("cp.async.commit_group;" ::: "memory");
    }

    float acc[2][4][4];
#pragma unroll
    for (int mi = 0; mi < 2; mi++)
#pragma unroll
        for (int nt = 0; nt < 4; nt++)
#pragma unroll
            for (int q = 0; q < 4; q++) acc[mi][nt][q] = 0.0f;

    for (int it = 0; it < nIter; it++) {
        if (it + 1 < nIter) asm volatile("cp.async.wait_group 1;" ::: "memory");
        else                asm volatile("cp.async.wait_group 0;" ::: "memory");
        __syncthreads();
        const uint32_t sA_hi = sbase + (it & 1) * STG_BYTES;
        const uint32_t sA_lo = sA_hi + 8192;
        const uint32_t sW_hi = sA_hi + 16384;
        const uint32_t sW_lo = sA_hi + 24576;

#pragma unroll
        for (int ks = 0; ks < 2; ks++) {
            uint32_t ah[2][4], al[2][4], bh[4][2], bl[4][2];
#pragma unroll
            for (int mi = 0; mi < 2; mi++) {
                int rr = wm * 32 + mi * 16 + (lane & 15);
                int kc = 2 * ks + (lane >> 4);
                uint32_t addr = swz(rr, kc);
                ldsm_x4(ah[mi], sA_hi + addr);
                ldsm_x4(al[mi], sA_lo + addr);
            }
#pragma unroll
            for (int njp = 0; njp < 2; njp++) {
                int seg = lane >> 3;
                int rr = wn * 32 + njp * 16 + ((seg >> 1) << 3) + (lane & 7);
                int kc = 2 * ks + (seg & 1);
                uint32_t addr = swz(rr, kc);
                uint32_t t0[4], t1[4];
                ldsm_x4(t0, sW_hi + addr);
                ldsm_x4(t1, sW_lo + addr);
                bh[njp * 2][0] = t0[0]; bh[njp * 2][1] = t0[1];
                bh[njp * 2 + 1][0] = t0[2]; bh[njp * 2 + 1][1] = t0[3];
                bl[njp * 2][0] = t1[0]; bl[njp * 2][1] = t1[1];
                bl[njp * 2 + 1][0] = t1[2]; bl[njp * 2 + 1][1] = t1[3];
            }
#pragma unroll
            for (int mi = 0; mi < 2; mi++)
#pragma unroll
                for (int nt = 0; nt < 4; nt++) {
                    mma16816(acc[mi][nt], ah[mi], bh[nt]);
                    mma16816(acc[mi][nt], ah[mi], bl[nt]);
                    mma16816(acc[mi][nt], al[mi], bh[nt]);
                }
        }
        __syncthreads();
        if (it + 2 < nIter) {
            issue(it & 1, kbase + (it + 2) * 32);
            asm volatile("cp.async.commit_group;" ::: "memory");
        }
    }

    // epilogue: direct register stores (2 contiguous floats per fragment row)
    const int g = lane >> 2, tig = lane & 3;
#pragma unroll
    for (int mi = 0; mi < 2; mi++) {
        int m0 = bm + wm * 32 + mi * 16 + g;
#pragma unroll
        for (int nt = 0; nt < 4; nt++) {
            int n = bn + wn * 32 + nt * 8 + tig * 2;
            if (n < Nvalid) {
                float b0 = bias ? bias[n] : 0.0f;
                float b1 = bias ? bias[n + 1] : 0.0f;
                float v0 = acc[mi][nt][0] + b0, v1 = acc[mi][nt][1] + b1;
                float v2 = acc[mi][nt][2] + b0, v3 = acc[mi][nt][3] + b1;
                if (ACT == 1) {
                    v0 = (v0 > 20.0f) ? v0 : log1pf(__expf(v0));
                    v1 = (v1 > 20.0f) ? v1 : log1pf(__expf(v1));
                    v2 = (v2 > 20.0f) ? v2 : log1pf(__expf(v2));
                    v3 = (v3 > 20.0f) ? v3 : log1pf(__expf(v3));
                }
                *(float2*)&Cz[(size_t)m0 * ldc + n] = make_float2(v0, v1);
                *(float2*)&Cz[(size_t)(m0 + 8) * ldc + n] = make_float2(v2, v3);
            }
        }
    }
}

// ---------------------------------------------------------------------------
// Depthwise causal conv1d (k=3) + bias + SiLU -> u (fp32 + hi/lo bf16)
// ---------------------------------------------------------------------------
__global__ void conv_silu_kernel(const float* __restrict__ cw,
                                 const float* __restrict__ cb) {
    int idx = blockIdx.x * blockDim.x + threadIdx.x;
    if (idx >= NTOK * DINNER) return;
    int d = idx & (DINNER - 1);
    int bl = idx >> 11;
    int l = bl & (LSEQ - 1);

    float w0 = __ldg(cw + d * 3 + 0);
    float w1 = __ldg(cw + d * 3 + 1);
    float w2 = __ldg(cw + d * 3 + 2);

    const float* base = g_xr + (size_t)bl * (2 * DINNER) + d;
    float acc = __ldg(cb + d) + w2 * base[0];
    if (l >= 1) acc = fmaf(w1, base[-(2 * DINNER)], acc);
    if (l >= 2) acc = fmaf(w0, base[-(4 * DINNER)], acc);
    float u = silu_f(acc);
    g_u[idx] = u;
    __nv_bfloat16 h, lo;
    split_bf16(u, h, lo);
    g_u_hi[idx] = h;
    g_u_lo[idx] = lo;
}

// ---------------------------------------------------------------------------
// Reduce x_proj K-split partials -> g_xp fp32 + hi/lo
// ---------------------------------------------------------------------------
__global__ void xp_reduce_kernel() {
    int i = blockIdx.x * blockDim.x + threadIdx.x;
    if (i >= NTOK * XPC) return;
    float s = 0.0f;
#pragma unroll
    for (int z = 0; z < XP_KSPLIT; z++)
        s += g_xp_part[(size_t)z * NTOK * XPC + i];
    g_xp[i] = s;
    __nv_bfloat16 h, lo;
    split_bf16(s, h, lo);
    g_xp_hi[i] = h;
    g_xp_lo[i] = lo;
}

// ---------------------------------------------------------------------------
// Gate: g = y * silu(res) -> hi/lo bf16 (A operand of out_proj)
// ---------------------------------------------------------------------------
__global__ void gate_kernel() {
    int idx = blockIdx.x * blockDim.x + threadIdx.x;
    if (idx >= NTOK * DINNER) return;
    int d = idx & (DINNER - 1);
    int bl = idx >> 11;
    float res = g_xr[(size_t)bl * (2 * DINNER) + DINNER + d];
    float v = g_y[idx] * silu_f(res);
    __nv_bfloat16 h, lo;
    split_bf16(v, h, lo);
    g_g_hi[idx] = h;
    g_g_lo[idx] = lo;
}

// ---------------------------------------------------------------------------
// Chunked selective scan
// ---------------------------------------------------------------------------
__global__ __launch_bounds__(128)
void scan_kernel(const float* __restrict__ A_log) {
    __shared__ float sBC[CHUNK][2 * NSTATE];
    const int b = blockIdx.z;
    const int c = blockIdx.y;
    const int d = blockIdx.x * 128 + threadIdx.x;
    const int l0 = c * CHUNK;
    const size_t row0 = (size_t)(b * LSEQ + l0);

    for (int i = threadIdx.x; i < CHUNK * 32; i += 128) {
        int t = i >> 5, j = i & 31;
        sBC[t][j] = g_xp[(row0 + t) * XPC + DTRANK + j];
    }

    float A[NSTATE];
#pragma unroll
    for (int n = 0; n < NSTATE; n++)
        A[n] = -__expf(__ldg(A_log + d * NSTATE + n));

    float s[NSTATE];
#pragma unroll
    for (int n = 0; n < NSTATE; n++) s[n] = 0.0f;
    __syncthreads();

    const float* dp = g_delta + row0 * DINNER + d;
    const float* up = g_u + row0 * DINNER + d;
    float* yp = g_y + row0 * DINNER + d;

    float dl = dp[0];
    float ut = up[0];
    for (int t = 0; t < CHUNK; t++) {
        float dln = 0.f, utn = 0.f;
        if (t + 1 < CHUNK) {
            dln = dp[(size_t)(t + 1) * DINNER];
            utn = up[(size_t)(t + 1) * DINNER];
        }
        float du = dl * ut;
        float accv = 0.0f;
#pragma unroll
        for (int n = 0; n < NSTATE; n++) {
            float a = __expf(dl * A[n]);
            s[n] = fmaf(a, s[n], du * sBC[t][n]);
            accv = fmaf(s[n], sBC[t][NSTATE + n], accv);
        }
        yp[(size_t)t * DINNER] = accv;
        dl = dln; ut = utn;
    }
}

// ---------------------------------------------------------------------------
// Host launch
// ---------------------------------------------------------------------------
extern "C" void kernel_launch(void* const* d_in, const int* in_sizes, int n_in,
                              void* d_out, int out_size) {
    const float* x      = (const float*)d_in[0];
    const float* W_in   = (const float*)d_in[1];
    const float* b_in   = (const float*)d_in[2];
    const float* conv_w = (const float*)d_in[3];
    const float* conv_b = (const float*)d_in[4];
    const float* W_x    = (const float*)d_in[5];
    const float* W_dt   = (const float*)d_in[6];
    const float* b_dt   = (const float*)d_in[7];
    const float* A_log  = (const float*)d_in[8];
    const float* W_out  = (const float*)d_in[9];
    const float* b_out  = (const float*)d_in[10];
    float* out = (float*)d_out;

    cudaFuncSetAttribute(gemm_mma_kernel<0>, cudaFuncAttributeMaxDynamicSharedMemorySize, GEMM_SMEM);
    cudaFuncSetAttribute(gemm_mma_kernel<1>, cudaFuncAttributeMaxDynamicSharedMemorySize, GEMM_SMEM);

    float *p_xr, *p_xp_part, *p_delta;
    cudaGetSymbolAddress((void**)&p_xr, g_xr);
    cudaGetSymbolAddress((void**)&p_xp_part, g_xp_part);
    cudaGetSymbolAddress((void**)&p_delta, g_delta);

    __nv_bfloat16 *xh, *xl, *wih, *wil, *wxh, *wxl, *wdh, *wdl, *woh, *wol;
    __nv_bfloat16 *uh, *ul, *xph, *xpl, *gh, *gl;
    cudaGetSymbolAddress((void**)&xh, g_x_hi);    cudaGetSymbolAddress((void**)&xl, g_x_lo);
    cudaGetSymbolAddress((void**)&wih, g_Win_hi); cudaGetSymbolAddress((void**)&wil, g_Win_lo);
    cudaGetSymbolAddress((void**)&wxh, g_Wx_hi);  cudaGetSymbolAddress((void**)&wxl, g_Wx_lo);
    cudaGetSymbolAddress((void**)&wdh, g_Wdt_hi); cudaGetSymbolAddress((void**)&wdl, g_Wdt_lo);
    cudaGetSymbolAddress((void**)&woh, g_Wout_hi); cudaGetSymbolAddress((void**)&wol, g_Wout_lo);
    cudaGetSymbolAddress((void**)&uh, g_u_hi);    cudaGetSymbolAddress((void**)&ul, g_u_lo);
    cudaGetSymbolAddress((void**)&xph, g_xp_hi);  cudaGetSymbolAddress((void**)&xpl, g_xp_lo);
    cudaGetSymbolAddress((void**)&gh, g_g_hi);    cudaGetSymbolAddress((void**)&gl, g_g_lo);

    auto cvt = [&](const float* src, __nv_bfloat16* h, __nv_bfloat16* l, int n) {
        int n4 = n / 4;
        cvt_pair_kernel<<<(n4 + 255) / 256, 256>>>(src, h, l, n4);
    };

    // 0) split-bf16 conversions of inputs/weights
    cvt(x,     xh,  xl,  NTOK * DMODEL);
    cvt(W_in,  wih, wil, 2 * DINNER * DMODEL);
    cvt(W_x,   wxh, wxl, XPC * DINNER);
    cvt(W_dt,  wdh, wdl, DINNER * DTRANK);
    cvt(W_out, woh, wol, DMODEL * DINNER);

    // 1) in_proj: xr = x @ W_in^T + b_in   (2048 x 4096, K=1024)
    gemm_mma_kernel<0><<<dim3(32, 16, 1), 512, GEMM_SMEM>>>(
        xh, xl, DMODEL, wih, wil, DMODEL, b_in, p_xr, 2 * DINNER, 2 * DINNER, 1024, 0);

    // 2) depthwise conv + SiLU -> u
    conv_silu_kernel<<<(NTOK * DINNER + 255) / 256, 256>>>(conv_w, conv_b);

    // 3) x_proj: xp = u @ W_x^T  (2048 x 96, K=2048), K-split 8 + reduce
    gemm_mma_kernel<0><<<dim3(1, 16, XP_KSPLIT), 512, GEMM_SMEM>>>(
        uh, ul, DINNER, wxh, wxl, DINNER, nullptr, p_xp_part, XPC, XPC,
        DINNER / XP_KSPLIT, (long)NTOK * XPC);
    xp_reduce_kernel<<<(NTOK * XPC + 255) / 256, 256>>>();

    // 4) delta = softplus(dlt @ W_dt^T + b_dt)  (2048 x 2048, K=64)
    gemm_mma_kernel<1><<<dim3(16, 16, 1), 512, GEMM_SMEM>>>(
        xph, xpl, XPC, wdh, wdl, DTRANK, b_dt, p_delta, DINNER, DINNER, 64, 0);

    // 5) chunked selective scan -> y
    scan_kernel<<<dim3(DINNER / 128, LSEQ / CHUNK, BSZ), 128>>>(A_log);

    // 6) gate: g = y * silu(res)
    gate_kernel<<<(NTOK * DINNER + 255) / 256, 256>>>();

    // 7) out = g @ W_out^T + b_out  (2048 x 1024, K=2048)
    gemm_mma_kernel<0><<<dim3(8, 16, 1), 512, GEMM_SMEM>>>(
        gh, gl, DINNER, woh, wol, DINNER, b_out, out, DMODEL, DMODEL, 2048, 0);
}